// round 5
// baseline (speedup 1.0000x reference)
#include <cuda_runtime.h>
#include <cstdint>
#include <math.h>

#define T_ROWS 8192
#define D_DIM  4096
#define E_DIM  64
#define TE     (T_ROWS * E_DIM)     // 524288

// k-major transposed W: g_Wt[k][e], 1 MB, L2-resident during GEMM.
__device__ float g_Wt[D_DIM * E_DIM];

// ---------------------------------------------------------------------------
// f32x2 packed math helpers (Blackwell sm_100+ PTX)
// ---------------------------------------------------------------------------
__device__ __forceinline__ unsigned long long packf2(float lo, float hi) {
    unsigned long long r;
    asm("mov.b64 %0, {%1, %2};" : "=l"(r) : "f"(lo), "f"(hi));
    return r;
}
__device__ __forceinline__ unsigned long long dupf(float v) { return packf2(v, v); }
__device__ __forceinline__ void ffma2(unsigned long long& c, unsigned long long a,
                                      unsigned long long b) {
    asm("fma.rn.f32x2 %0, %1, %2, %0;" : "+l"(c) : "l"(a), "l"(b));
}
__device__ __forceinline__ void unpackf2(unsigned long long p, float& lo, float& hi) {
    asm("mov.b64 {%0, %1}, %2;" : "=f"(lo), "=f"(hi) : "l"(p));
}

__device__ __forceinline__ unsigned sptr(const void* p) {
    return (unsigned)__cvta_generic_to_shared(p);
}

// ---------------------------------------------------------------------------
// Kernel 0: transpose W[E][D] -> g_Wt[D][E] (coalesced both sides via smem)
// ---------------------------------------------------------------------------
__global__ void k_transpose(const float* __restrict__ W) {
    __shared__ float s[64][33];
    const int k0 = blockIdx.x * 32;
    const int tid = threadIdx.x;
#pragma unroll
    for (int j = 0; j < 8; j++) {
        int idx = tid + 256 * j;            // 0..2047
        int e = idx >> 5, kk = idx & 31;
        s[e][kk] = W[(size_t)e * D_DIM + k0 + kk];
    }
    __syncthreads();
#pragma unroll
    for (int j = 0; j < 8; j++) {
        int idx = tid + 256 * j;
        int kk = idx >> 6, e = idx & 63;
        g_Wt[(size_t)(k0 + kk) * E_DIM + e] = s[e][kk];
    }
}

// ---------------------------------------------------------------------------
// Kernel 1: GEMM  logits[T][E] = h[T][D] @ Wt[D][E] + bias
//   BM=64 rows/CTA, 128 threads (tx 0..15 over E/4, ty 0..7),
//   thread owns rows {ty + 8i} x cols {tx*4..tx*4+3}
//   h tile double-buffered via cp.async; W streamed from L2 (LDG.128)
//   accumulate in packed f32x2 (pairs along M)
// ---------------------------------------------------------------------------
#define HS_STRIDE 36   // 64 rows * 36 floats; 36*4=144B (16B multiple), 36 % 32 = 4

__global__ __launch_bounds__(128, 1)
void k_gemm(const float* __restrict__ h, const float* __restrict__ bias,
            float* __restrict__ logits) {
    __shared__ __align__(16) float hs[2][64 * HS_STRIDE];
    const int tid = threadIdx.x;
    const int tx = tid & 15;
    const int ty = tid >> 4;
    const int row0 = blockIdx.x * 64;

#define PREFETCH(KB, BUF) do {                                                   \
    unsigned _base = sptr(&hs[(BUF)][0]);                                        \
    _Pragma("unroll")                                                            \
    for (int _j = 0; _j < 4; _j++) {                                             \
        int _c = tid + 128 * _j;            /* 0..511 float4 chunks */           \
        int _r = _c >> 3;                   /* row 0..63 */                      \
        int _kq = (_c & 7) * 4;             /* k offset 0,4,..,28 */             \
        unsigned _dst = _base + (unsigned)((_r * HS_STRIDE + _kq) * 4);          \
        const float* _src = h + (size_t)(row0 + _r) * D_DIM + (KB) * 32 + _kq;   \
        asm volatile("cp.async.ca.shared.global [%0], [%1], 16;"                 \
                     :: "r"(_dst), "l"(_src));                                   \
    }                                                                            \
    asm volatile("cp.async.commit_group;");                                      \
} while (0)

    unsigned long long acc[4][4];   // [m-pair j][n]; pair = rows (ty+16j, ty+16j+8)
#pragma unroll
    for (int i = 0; i < 4; i++)
#pragma unroll
        for (int j = 0; j < 4; j++) acc[i][j] = 0ull;

    PREFETCH(0, 0);

    const int NT = D_DIM / 32;  // 128
    for (int kb = 0; kb < NT; kb++) {
        const int buf = kb & 1;
        if (kb + 1 < NT) {
            PREFETCH(kb + 1, buf ^ 1);
            asm volatile("cp.async.wait_group 1;");
        } else {
            asm volatile("cp.async.wait_group 0;");
        }
        __syncthreads();

        const float* wp = g_Wt + (size_t)kb * 32 * E_DIM + tx * 4;
        const float* hp = &hs[buf][ty * HS_STRIDE];   // row ty, +8*HS_STRIDE per i

#pragma unroll
        for (int k = 0; k < 32; k++) {
            const float4 b = *(const float4*)(wp + (size_t)k * E_DIM);
            unsigned long long b0 = dupf(b.x), b1 = dupf(b.y),
                               b2 = dupf(b.z), b3 = dupf(b.w);
#pragma unroll
            for (int j = 0; j < 4; j++) {
                float a0 = hp[(16 * j) * HS_STRIDE + k];       // row ty+16j
                float a1 = hp[(16 * j + 8) * HS_STRIDE + k];   // row ty+16j+8
                unsigned long long ap = packf2(a0, a1);
                ffma2(acc[j][0], ap, b0);
                ffma2(acc[j][1], ap, b1);
                ffma2(acc[j][2], ap, b2);
                ffma2(acc[j][3], ap, b3);
            }
        }
        __syncthreads();
    }

    // epilogue: add bias, store fp32 logits
    const float4 bv = *(const float4*)(bias + tx * 4);
#pragma unroll
    for (int j = 0; j < 4; j++) {
        float lo[4], hi[4];
#pragma unroll
        for (int n = 0; n < 4; n++) unpackf2(acc[j][n], lo[n], hi[n]);
        int rlo = row0 + ty + 16 * j;
        int rhi = rlo + 8;
        float4 o0 = make_float4(lo[0] + bv.x, lo[1] + bv.y, lo[2] + bv.z, lo[3] + bv.w);
        float4 o1 = make_float4(hi[0] + bv.x, hi[1] + bv.y, hi[2] + bv.z, hi[3] + bv.w);
        *(float4*)(logits + (size_t)rlo * E_DIM + tx * 4) = o0;
        *(float4*)(logits + (size_t)rhi * E_DIM + tx * 4) = o1;
    }
#undef PREFETCH
}

// ---------------------------------------------------------------------------
// JAX threefry2x32 with key = jax.random.key(42)  ->  (k1=0, k2=42)
// ---------------------------------------------------------------------------
__device__ __forceinline__ uint32_t rotl32(uint32_t x, int r) {
    return __funnelshift_l(x, x, r);
}

__device__ __forceinline__ void threefry_42(uint32_t c0, uint32_t c1,
                                            uint32_t& o0, uint32_t& o1) {
    const uint32_t ks0 = 0u, ks1 = 42u, ks2 = 0x1BD11BDAu ^ 0u ^ 42u;
    uint32_t x0 = c0 + ks0, x1 = c1 + ks1;
#define TF_R(r) { x0 += x1; x1 = rotl32(x1, (r)); x1 ^= x0; }
    TF_R(13) TF_R(15) TF_R(26) TF_R(6);   x0 += ks1; x1 += ks2 + 1u;
    TF_R(17) TF_R(29) TF_R(16) TF_R(24);  x0 += ks2; x1 += ks0 + 2u;
    TF_R(13) TF_R(15) TF_R(26) TF_R(6);   x0 += ks0; x1 += ks1 + 3u;
    TF_R(17) TF_R(29) TF_R(16) TF_R(24);  x0 += ks1; x1 += ks2 + 4u;
    TF_R(13) TF_R(15) TF_R(26) TF_R(6);   x0 += ks2; x1 += ks0 + 5u;
#undef TF_R
    o0 = x0; o1 = x1;
}

// jax_threefry_partitionable=True (default since JAX 0.4.30) random_bits path:
// per flat element i, counter = uint64 iota -> lanes (hi = i>>32 = 0, lo = i),
// bits32 = out0 ^ out1. Then uniform: (bits>>9 | 0x3f800000) - 1, affine to
// [1e-6, 1-1e-6] (separate mul/add like XLA), clamp at minval, double-log.
__device__ __forceinline__ float gumbel_at(uint32_t i) {
    uint32_t o0, o1;
    threefry_42(0u, i, o0, o1);
    uint32_t bits = o0 ^ o1;
    float f = __uint_as_float((bits >> 9) | 0x3F800000u) - 1.0f;   // [0,1)
    const float minv  = (float)1e-6;
    const float maxv  = (float)(1.0 - 1e-6);
    const float scale = maxv - minv;                 // compile-time f32, like XLA
    float u = __fadd_rn(__fmul_rn(f, scale), minv);  // no FMA contraction (match XLA)
    u = fmaxf(minv, u);
    return -logf(-logf(u));
}

// ---------------------------------------------------------------------------
// Kernel 2: per-row softmax + Gumbel top-k mask. One warp per row (E=64: 2/lane)
// ---------------------------------------------------------------------------
__global__ __launch_bounds__(256)
void k_router(const float* __restrict__ logits, const int* __restrict__ kin,
              float* __restrict__ mask, float* __restrict__ weight) {
    const int gw = (int)((blockIdx.x * blockDim.x + threadIdx.x) >> 5);
    const int lane = threadIdx.x & 31;
    if (gw >= T_ROWS) return;

    int K = 8;
    if (kin) { K = *kin; if (K < 0) K = 0; if (K > E_DIM) K = E_DIM; }

    const float* lrow = logits + (size_t)gw * E_DIM;
    float l0 = lrow[lane];
    float l1 = lrow[lane + 32];

    // softmax on clean logits
    float mx = fmaxf(l0, l1);
#pragma unroll
    for (int o = 16; o; o >>= 1) mx = fmaxf(mx, __shfl_xor_sync(0xffffffffu, mx, o));
    float p0 = expf(l0 - mx), p1 = expf(l1 - mx);
    float s = p0 + p1;
#pragma unroll
    for (int o = 16; o; o >>= 1) s += __shfl_xor_sync(0xffffffffu, s, o);
    weight[(size_t)gw * E_DIM + lane]      = p0 / s;
    weight[(size_t)gw * E_DIM + lane + 32] = p1 / s;

    // Gumbel-perturbed selection scores
    const uint32_t base = (uint32_t)gw * 64u;
    float s0 = l0 + gumbel_at(base + (uint32_t)lane);
    float s1 = l1 + gumbel_at(base + (uint32_t)lane + 32u);

    const float NEG_INF = __int_as_float(0xff800000);
    const int e0 = lane, e1 = lane + 32;
    float m0 = 0.0f, m1 = 0.0f;

    for (int kk = 0; kk < K; kk++) {
        float v = s0; int ii = e0;
        if (s1 > v) { v = s1; ii = e1; }   // e1 > e0, tie keeps e0 (lower index)
#pragma unroll
        for (int o = 16; o; o >>= 1) {
            float ov = __shfl_xor_sync(0xffffffffu, v, o);
            int   oi = __shfl_xor_sync(0xffffffffu, ii, o);
            if (ov > v || (ov == v && oi < ii)) { v = ov; ii = oi; }
        }
        if (ii == e0)      { m0 = 1.0f; s0 = NEG_INF; }
        else if (ii == e1) { m1 = 1.0f; s1 = NEG_INF; }
    }

    mask[(size_t)gw * E_DIM + lane]      = m0;
    mask[(size_t)gw * E_DIM + lane + 32] = m1;
}

// ---------------------------------------------------------------------------
// launch: transpose -> GEMM (logits into out slice) -> router
// out layout (f32): [ mask (T*E) | weight (T*E) | logits (T*E) ]
// ---------------------------------------------------------------------------
extern "C" void kernel_launch(void* const* d_in, const int* in_sizes, int n_in,
                              void* d_out, int out_size) {
    const float* h    = (const float*)d_in[0];
    const float* W    = (const float*)d_in[1];
    const float* bias = (const float*)d_in[2];
    const int*   kin  = (n_in > 3 && in_sizes[3] == 1) ? (const int*)d_in[3] : nullptr;

    float* out    = (float*)d_out;
    float* mask   = out;
    float* weight = out + TE;
    float* logits = out + 2 * TE;

    k_transpose<<<D_DIM / 32, 256>>>(W);
    k_gemm<<<T_ROWS / 64, 128>>>(h, bias, logits);
    k_router<<<(T_ROWS * 32) / 256, 256>>>(logits, kin, mask, weight);
}

// round 9
// speedup vs baseline: 1.4585x; 1.4585x over previous
#include <cuda_runtime.h>
#include <cstdint>
#include <math.h>

#define T_ROWS 8192
#define D_DIM  4096
#define E_DIM  64
#define TE     (T_ROWS * E_DIM)     // 524288

// k-PAIRED transposed W: g_Wtp[kp][e*2+parity] = W[e][2*kp+parity], 1 MB (L2-resident).
// A 64-bit load at [kp][2e] yields the f32x2 pair (W_k_even, W_k_odd) for expert e.
__device__ float g_Wtp[D_DIM * E_DIM];

// ---------------------------------------------------------------------------
// f32x2 packed math helpers (Blackwell sm_100+ PTX)
// ---------------------------------------------------------------------------
__device__ __forceinline__ void ffma2(unsigned long long& c, unsigned long long a,
                                      unsigned long long b) {
    asm("fma.rn.f32x2 %0, %1, %2, %0;" : "+l"(c) : "l"(a), "l"(b));
}
__device__ __forceinline__ void unpackf2(unsigned long long p, float& lo, float& hi) {
    asm("mov.b64 {%0, %1}, %2;" : "=f"(lo), "=f"(hi) : "l"(p));
}
__device__ __forceinline__ unsigned sptr(const void* p) {
    return (unsigned)__cvta_generic_to_shared(p);
}

// ---------------------------------------------------------------------------
// Kernel 0: W[E][D] -> k-paired g_Wtp (coalesced both sides via smem)
// ---------------------------------------------------------------------------
__global__ void k_transpose(const float* __restrict__ W) {
    __shared__ float s[64][34];              // pad 34: conflict-free both phases
    const int k0 = blockIdx.x * 32;
    const int tid = threadIdx.x;
#pragma unroll
    for (int j = 0; j < 8; j++) {
        int idx = tid + 256 * j;             // 0..2047
        int e = idx >> 5, kk = idx & 31;
        s[e][kk] = W[(size_t)e * D_DIM + k0 + kk];
    }
    __syncthreads();
#pragma unroll
    for (int j = 0; j < 8; j++) {
        int idx = tid + 256 * j;             // flat paired-layout offset
        int kp_l = idx >> 7;                 // local k-pair 0..15
        int rem  = idx & 127;                // e*2 + parity
        int e    = rem >> 1;
        int par  = rem & 1;
        g_Wtp[(size_t)(k0 / 2 + kp_l) * 128 + rem] = s[e][kp_l * 2 + par];
    }
}

// ---------------------------------------------------------------------------
// Kernel 1: GEMM  logits[T][E] = h[T][D] @ W^T + bias
//   BM=64 rows/CTA, 256 threads (tx 0..15 -> cols 4tx..4tx+3, ty 0..15 ->
//   rows ty+16i). f32x2 lanes = (even k, odd k) partial sums: A pairs via
//   LDS.64 of consecutive k, B pairs direct from k-paired smem tile.
//   ws tile row stride is 128 FLOATS (512 B): index with float offsets only.
//   3-stage cp.async, 1 barrier per k-tile.
// ---------------------------------------------------------------------------
#define NT 128           // 4096 / 32 k-tiles

__global__ __launch_bounds__(256, 1)
void k_gemm(const float* __restrict__ h, const float* __restrict__ bias,
            float* __restrict__ logits) {
    __shared__ __align__(16) float hs[3][2048];   // 64 rows x 32 k
    __shared__ __align__(16) float ws[3][2048];   // 16 kp x 128 (e*2+par)
    const int tid = threadIdx.x;
    const int tx = tid & 15;
    const int ty = tid >> 4;
    const int row0 = blockIdx.x * 64;

#define PF(KB, S) do {                                                           \
    _Pragma("unroll")                                                            \
    for (int _j = 0; _j < 2; _j++) {                                             \
        int _c = tid + 256 * _j;             /* 0..511 float4 chunks */          \
        int _r = _c >> 3;                                                        \
        int _kq = (_c & 7) * 4;                                                  \
        unsigned _dA = sptr(&hs[(S)][_r * 32 + _kq]);                            \
        const float* _sA = h + (size_t)(row0 + _r) * D_DIM + (KB) * 32 + _kq;    \
        asm volatile("cp.async.ca.shared.global [%0], [%1], 16;"                 \
                     :: "r"(_dA), "l"(_sA));                                     \
        unsigned _dB = sptr(&ws[(S)][_c * 4]);                                   \
        const float* _sB = g_Wtp + (size_t)(KB) * 2048 + _c * 4;                 \
        asm volatile("cp.async.ca.shared.global [%0], [%1], 16;"                 \
                     :: "r"(_dB), "l"(_sB));                                     \
    }                                                                            \
    asm volatile("cp.async.commit_group;");                                      \
} while (0)

    unsigned long long acc[4][4];   // [row i][col j], lanes = (even-k, odd-k) sums
#pragma unroll
    for (int i = 0; i < 4; i++)
#pragma unroll
        for (int j = 0; j < 4; j++) acc[i][j] = 0ull;

    PF(0, 0);
    PF(1, 1);

    for (int kb = 0; kb < NT; kb++) {
        if (kb < NT - 1) asm volatile("cp.async.wait_group 1;");
        else             asm volatile("cp.async.wait_group 0;");
        __syncthreads();   // tile kb visible; tile (kb-1) fully consumed by all
        if (kb + 2 < NT) PF(kb + 2, (kb + 2) % 3);   // refills stage (kb-1)%3

        const int s = kb % 3;
        const unsigned long long* a0 =
            (const unsigned long long*)&hs[s][(ty) * 32];
        const unsigned long long* a1 =
            (const unsigned long long*)&hs[s][(ty + 16) * 32];
        const unsigned long long* a2 =
            (const unsigned long long*)&hs[s][(ty + 32) * 32];
        const unsigned long long* a3 =
            (const unsigned long long*)&hs[s][(ty + 48) * 32];
        const float* wrow = &ws[s][8 * tx];   // experts 4tx..4tx+3, paired floats

#pragma unroll
        for (int kp = 0; kp < 16; kp++) {
            unsigned long long ra0 = a0[kp], ra1 = a1[kp],
                               ra2 = a2[kp], ra3 = a3[kp];
            // row kp of ws = kp*128 floats. b01 = experts (4tx,4tx+1) pairs,
            // b23 = experts (4tx+2,4tx+3) pairs.
            ulonglong2 b01 = *(const ulonglong2*)(wrow + kp * 128);
            ulonglong2 b23 = *(const ulonglong2*)(wrow + kp * 128 + 4);
            ffma2(acc[0][0], ra0, b01.x); ffma2(acc[0][1], ra0, b01.y);
            ffma2(acc[0][2], ra0, b23.x); ffma2(acc[0][3], ra0, b23.y);
            ffma2(acc[1][0], ra1, b01.x); ffma2(acc[1][1], ra1, b01.y);
            ffma2(acc[1][2], ra1, b23.x); ffma2(acc[1][3], ra1, b23.y);
            ffma2(acc[2][0], ra2, b01.x); ffma2(acc[2][1], ra2, b01.y);
            ffma2(acc[2][2], ra2, b23.x); ffma2(acc[2][3], ra2, b23.y);
            ffma2(acc[3][0], ra3, b01.x); ffma2(acc[3][1], ra3, b01.y);
            ffma2(acc[3][2], ra3, b23.x); ffma2(acc[3][3], ra3, b23.y);
        }
    }

    // epilogue: lanes (even,odd) -> scalar, add bias, store fp32 logits
    const float4 bv = *(const float4*)(bias + tx * 4);
#pragma unroll
    for (int i = 0; i < 4; i++) {
        float v[4];
#pragma unroll
        for (int j = 0; j < 4; j++) {
            float lo, hi;
            unpackf2(acc[i][j], lo, hi);
            v[j] = lo + hi;
        }
        int r = row0 + ty + 16 * i;
        float4 o = make_float4(v[0] + bv.x, v[1] + bv.y, v[2] + bv.z, v[3] + bv.w);
        *(float4*)(logits + (size_t)r * E_DIM + tx * 4) = o;
    }
#undef PF
}

// ---------------------------------------------------------------------------
// JAX threefry2x32, key = jax.random.key(42) -> (0, 42)
// ---------------------------------------------------------------------------
__device__ __forceinline__ uint32_t rotl32(uint32_t x, int r) {
    return __funnelshift_l(x, x, r);
}

__device__ __forceinline__ void threefry_42(uint32_t c0, uint32_t c1,
                                            uint32_t& o0, uint32_t& o1) {
    const uint32_t ks0 = 0u, ks1 = 42u, ks2 = 0x1BD11BDAu ^ 0u ^ 42u;
    uint32_t x0 = c0 + ks0, x1 = c1 + ks1;
#define TF_R(r) { x0 += x1; x1 = rotl32(x1, (r)); x1 ^= x0; }
    TF_R(13) TF_R(15) TF_R(26) TF_R(6);   x0 += ks1; x1 += ks2 + 1u;
    TF_R(17) TF_R(29) TF_R(16) TF_R(24);  x0 += ks2; x1 += ks0 + 2u;
    TF_R(13) TF_R(15) TF_R(26) TF_R(6);   x0 += ks0; x1 += ks1 + 3u;
    TF_R(17) TF_R(29) TF_R(16) TF_R(24);  x0 += ks1; x1 += ks2 + 4u;
    TF_R(13) TF_R(15) TF_R(26) TF_R(6);   x0 += ks2; x1 += ks0 + 5u;
#undef TF_R
    o0 = x0; o1 = x1;
}

// jax_threefry_partitionable=True path: counter = uint64 iota -> lanes (0, i),
// bits32 = out0 ^ out1; uniform via (bits>>9 | 0x3f800000) - 1, affine
// (separate mul/add like XLA), clamp at minval, then -log(-log(u)).
__device__ __forceinline__ float gumbel_at(uint32_t i) {
    uint32_t o0, o1;
    threefry_42(0u, i, o0, o1);
    uint32_t bits = o0 ^ o1;
    float f = __uint_as_float((bits >> 9) | 0x3F800000u) - 1.0f;   // [0,1)
    const float minv  = (float)1e-6;
    const float maxv  = (float)(1.0 - 1e-6);
    const float scale = maxv - minv;
    float u = __fadd_rn(__fmul_rn(f, scale), minv);  // no FMA contraction
    u = fmaxf(minv, u);
    return -logf(-logf(u));
}

// ---------------------------------------------------------------------------
// Kernel 2: per-row softmax + Gumbel top-k mask. One warp per row.
// ---------------------------------------------------------------------------
__global__ __launch_bounds__(256)
void k_router(const float* __restrict__ logits, const int* __restrict__ kin,
              float* __restrict__ mask, float* __restrict__ weight) {
    const int gw = (int)((blockIdx.x * blockDim.x + threadIdx.x) >> 5);
    const int lane = threadIdx.x & 31;
    if (gw >= T_ROWS) return;

    int K = 8;
    if (kin) { K = *kin; if (K < 0) K = 0; if (K > E_DIM) K = E_DIM; }

    const float* lrow = logits + (size_t)gw * E_DIM;
    float l0 = lrow[lane];
    float l1 = lrow[lane + 32];

    // softmax on clean logits
    float mx = fmaxf(l0, l1);
#pragma unroll
    for (int o = 16; o; o >>= 1) mx = fmaxf(mx, __shfl_xor_sync(0xffffffffu, mx, o));
    float p0 = expf(l0 - mx), p1 = expf(l1 - mx);
    float s = p0 + p1;
#pragma unroll
    for (int o = 16; o; o >>= 1) s += __shfl_xor_sync(0xffffffffu, s, o);
    weight[(size_t)gw * E_DIM + lane]      = p0 / s;
    weight[(size_t)gw * E_DIM + lane + 32] = p1 / s;

    // Gumbel-perturbed selection scores
    const uint32_t base = (uint32_t)gw * 64u;
    float s0 = l0 + gumbel_at(base + (uint32_t)lane);
    float s1 = l1 + gumbel_at(base + (uint32_t)lane + 32u);

    const float NEG_INF = __int_as_float(0xff800000);
    const int e0 = lane, e1 = lane + 32;
    float m0 = 0.0f, m1 = 0.0f;

    for (int kk = 0; kk < K; kk++) {
        float v = s0; int ii = e0;
        if (s1 > v) { v = s1; ii = e1; }   // tie keeps lower index
#pragma unroll
        for (int o = 16; o; o >>= 1) {
            float ov = __shfl_xor_sync(0xffffffffu, v, o);
            int   oi = __shfl_xor_sync(0xffffffffu, ii, o);
            if (ov > v || (ov == v && oi < ii)) { v = ov; ii = oi; }
        }
        if (ii == e0)      { m0 = 1.0f; s0 = NEG_INF; }
        else if (ii == e1) { m1 = 1.0f; s1 = NEG_INF; }
    }

    mask[(size_t)gw * E_DIM + lane]      = m0;
    mask[(size_t)gw * E_DIM + lane + 32] = m1;
}

// ---------------------------------------------------------------------------
// launch: transpose -> GEMM (logits into out slice) -> router
// out layout (f32): [ mask (T*E) | weight (T*E) | logits (T*E) ]
// ---------------------------------------------------------------------------
extern "C" void kernel_launch(void* const* d_in, const int* in_sizes, int n_in,
                              void* d_out, int out_size) {
    const float* h    = (const float*)d_in[0];
    const float* W    = (const float*)d_in[1];
    const float* bias = (const float*)d_in[2];
    const int*   kin  = (n_in > 3 && in_sizes[3] == 1) ? (const int*)d_in[3] : nullptr;

    float* out    = (float*)d_out;
    float* mask   = out;
    float* weight = out + TE;
    float* logits = out + 2 * TE;

    k_transpose<<<D_DIM / 32, 256>>>(W);
    k_gemm<<<T_ROWS / 64, 256>>>(h, bias, logits);
    k_router<<<(T_ROWS * 32) / 256, 256>>>(logits, kin, mask, weight);
}

// round 11
// speedup vs baseline: 2.0413x; 1.3996x over previous
#include <cuda_runtime.h>
#include <cstdint>
#include <math.h>

#define T_ROWS 8192
#define D_DIM  4096
#define E_DIM  64
#define TE     (T_ROWS * E_DIM)     // 524288

// k-PAIRED transposed W: g_Wtp[kp][e*2+parity] = W[e][2*kp+parity], 1 MB (L2-resident).
__device__ float g_Wtp[D_DIM * E_DIM];

// ---------------------------------------------------------------------------
// f32x2 packed math helpers
// ---------------------------------------------------------------------------
__device__ __forceinline__ void ffma2(unsigned long long& c, unsigned long long a,
                                      unsigned long long b) {
    asm("fma.rn.f32x2 %0, %1, %2, %0;" : "+l"(c) : "l"(a), "l"(b));
}
__device__ __forceinline__ void unpackf2(unsigned long long p, float& lo, float& hi) {
    asm("mov.b64 {%0, %1}, %2;" : "=f"(lo), "=f"(hi) : "l"(p));
}
__device__ __forceinline__ unsigned sptr(const void* p) {
    return (unsigned)__cvta_generic_to_shared(p);
}

// ---------------------------------------------------------------------------
// Kernel 0: W[E][D] -> k-paired g_Wtp (coalesced both sides via smem)
// ---------------------------------------------------------------------------
__global__ void k_transpose(const float* __restrict__ W) {
    __shared__ float s[64][34];
    const int k0 = blockIdx.x * 32;
    const int tid = threadIdx.x;
#pragma unroll
    for (int j = 0; j < 8; j++) {
        int idx = tid + 256 * j;
        int e = idx >> 5, kk = idx & 31;
        s[e][kk] = W[(size_t)e * D_DIM + k0 + kk];
    }
    __syncthreads();
#pragma unroll
    for (int j = 0; j < 8; j++) {
        int idx = tid + 256 * j;
        int kp_l = idx >> 7;
        int rem  = idx & 127;
        int e    = rem >> 1;
        int par  = rem & 1;
        g_Wtp[(size_t)(k0 / 2 + kp_l) * 128 + rem] = s[e][kp_l * 2 + par];
    }
}

// ---------------------------------------------------------------------------
// Kernel 1: GEMM  logits[T][E] = h[T][D] @ W^T + bias
//   BM=64, 256 threads (tx 0..15 -> cols 4tx..4tx+3, ty 0..15 -> rows ty+16i).
//   f32x2 lanes = (even k, odd k) partial sums.
//   hs rows padded to 36 floats (A LDS.128 = 2 k-pairs, bank-clean).
//   ws rows (128 floats = 32 quads) stored with quad swizzle q ^ (q>>3):
//   both per-warp B LDS.128 instructions hit every bank-quad residue exactly
//   twice -> conflict-free. 3-stage cp.async, 1 barrier/tile.
// ---------------------------------------------------------------------------
#define NT 128           // 4096 / 32 k-tiles
#define HSS 36           // hs row stride in floats

__global__ __launch_bounds__(256, 1)
void k_gemm(const float* __restrict__ h, const float* __restrict__ bias,
            float* __restrict__ logits) {
    __shared__ __align__(16) float hs[3][64 * HSS];   // 64 rows x 32 k (padded)
    __shared__ __align__(16) float ws[3][2048];       // 16 kp-rows x 128, swizzled
    const int tid = threadIdx.x;
    const int tx = tid & 15;
    const int ty = tid >> 4;
    const int row0 = blockIdx.x * 64;

    // per-thread swizzled B quad offsets (floats) within a 128-float row
    const int o01 = (((2 * tx)     ^ (tx >> 2)) * 4);
    const int o23 = (((2 * tx + 1) ^ (tx >> 2)) * 4);

#define PF(KB, S) do {                                                           \
    _Pragma("unroll")                                                            \
    for (int _j = 0; _j < 2; _j++) {                                             \
        int _c = tid + 256 * _j;             /* 0..511 quad chunks */            \
        int _r = _c >> 3;                                                        \
        int _kq = (_c & 7) * 4;                                                  \
        unsigned _dA = sptr(&hs[(S)][_r * HSS + _kq]);                           \
        const float* _sA = h + (size_t)(row0 + _r) * D_DIM + (KB) * 32 + _kq;    \
        asm volatile("cp.async.ca.shared.global [%0], [%1], 16;"                 \
                     :: "r"(_dA), "l"(_sA));                                     \
        int _kp = _c >> 5;                   /* B row 0..15 */                   \
        int _qr = _c & 31;                   /* quad in row */                   \
        int _qs = _qr ^ (_qr >> 3);          /* swizzled quad */                 \
        unsigned _dB = sptr(&ws[(S)][_kp * 128 + _qs * 4]);                      \
        const float* _sB = g_Wtp + (size_t)(KB) * 2048 + _c * 4;                 \
        asm volatile("cp.async.ca.shared.global [%0], [%1], 16;"                 \
                     :: "r"(_dB), "l"(_sB));                                     \
    }                                                                            \
    asm volatile("cp.async.commit_group;");                                      \
} while (0)

    unsigned long long acc[4][4];   // [row i][col j], lanes = (even-k, odd-k)
#pragma unroll
    for (int i = 0; i < 4; i++)
#pragma unroll
        for (int j = 0; j < 4; j++) acc[i][j] = 0ull;

    PF(0, 0);
    PF(1, 1);

    for (int kb = 0; kb < NT; kb++) {
        if (kb < NT - 1) asm volatile("cp.async.wait_group 1;");
        else             asm volatile("cp.async.wait_group 0;");
        __syncthreads();
        if (kb + 2 < NT) PF(kb + 2, (kb + 2) % 3);

        const int s = kb % 3;
        const float* hb = &hs[s][0];
        const float* wb = &ws[s][0];

#pragma unroll
        for (int kq = 0; kq < 8; kq++) {   // one quad = k-pairs 2kq, 2kq+1
            ulonglong2 A0 = *(const ulonglong2*)(hb + (ty)      * HSS + 4 * kq);
            ulonglong2 A1 = *(const ulonglong2*)(hb + (ty + 16) * HSS + 4 * kq);
            ulonglong2 A2 = *(const ulonglong2*)(hb + (ty + 32) * HSS + 4 * kq);
            ulonglong2 A3 = *(const ulonglong2*)(hb + (ty + 48) * HSS + 4 * kq);
            ulonglong2 B0a = *(const ulonglong2*)(wb + (2 * kq)     * 128 + o01);
            ulonglong2 B0b = *(const ulonglong2*)(wb + (2 * kq)     * 128 + o23);
            ulonglong2 B1a = *(const ulonglong2*)(wb + (2 * kq + 1) * 128 + o01);
            ulonglong2 B1b = *(const ulonglong2*)(wb + (2 * kq + 1) * 128 + o23);

            // k-pair 2kq
            ffma2(acc[0][0], A0.x, B0a.x); ffma2(acc[0][1], A0.x, B0a.y);
            ffma2(acc[0][2], A0.x, B0b.x); ffma2(acc[0][3], A0.x, B0b.y);
            ffma2(acc[1][0], A1.x, B0a.x); ffma2(acc[1][1], A1.x, B0a.y);
            ffma2(acc[1][2], A1.x, B0b.x); ffma2(acc[1][3], A1.x, B0b.y);
            ffma2(acc[2][0], A2.x, B0a.x); ffma2(acc[2][1], A2.x, B0a.y);
            ffma2(acc[2][2], A2.x, B0b.x); ffma2(acc[2][3], A2.x, B0b.y);
            ffma2(acc[3][0], A3.x, B0a.x); ffma2(acc[3][1], A3.x, B0a.y);
            ffma2(acc[3][2], A3.x, B0b.x); ffma2(acc[3][3], A3.x, B0b.y);
            // k-pair 2kq+1
            ffma2(acc[0][0], A0.y, B1a.x); ffma2(acc[0][1], A0.y, B1a.y);
            ffma2(acc[0][2], A0.y, B1b.x); ffma2(acc[0][3], A0.y, B1b.y);
            ffma2(acc[1][0], A1.y, B1a.x); ffma2(acc[1][1], A1.y, B1a.y);
            ffma2(acc[1][2], A1.y, B1b.x); ffma2(acc[1][3], A1.y, B1b.y);
            ffma2(acc[2][0], A2.y, B1a.x); ffma2(acc[2][1], A2.y, B1a.y);
            ffma2(acc[2][2], A2.y, B1b.x); ffma2(acc[2][3], A2.y, B1b.y);
            ffma2(acc[3][0], A3.y, B1a.x); ffma2(acc[3][1], A3.y, B1a.y);
            ffma2(acc[3][2], A3.y, B1b.x); ffma2(acc[3][3], A3.y, B1b.y);
        }
    }

    // epilogue: lanes (even,odd) -> scalar, add bias, store fp32 logits
    const float4 bv = *(const float4*)(bias + tx * 4);
#pragma unroll
    for (int i = 0; i < 4; i++) {
        float v[4];
#pragma unroll
        for (int j = 0; j < 4; j++) {
            float lo, hi;
            unpackf2(acc[i][j], lo, hi);
            v[j] = lo + hi;
        }
        int r = row0 + ty + 16 * i;
        float4 o = make_float4(v[0] + bv.x, v[1] + bv.y, v[2] + bv.z, v[3] + bv.w);
        *(float4*)(logits + (size_t)r * E_DIM + tx * 4) = o;
    }
#undef PF
}

// ---------------------------------------------------------------------------
// JAX threefry2x32, key = jax.random.key(42) -> (0, 42)
// ---------------------------------------------------------------------------
__device__ __forceinline__ uint32_t rotl32(uint32_t x, int r) {
    return __funnelshift_l(x, x, r);
}

__device__ __forceinline__ void threefry_42(uint32_t c0, uint32_t c1,
                                            uint32_t& o0, uint32_t& o1) {
    const uint32_t ks0 = 0u, ks1 = 42u, ks2 = 0x1BD11BDAu ^ 0u ^ 42u;
    uint32_t x0 = c0 + ks0, x1 = c1 + ks1;
#define TF_R(r) { x0 += x1; x1 = rotl32(x1, (r)); x1 ^= x0; }
    TF_R(13) TF_R(15) TF_R(26) TF_R(6);   x0 += ks1; x1 += ks2 + 1u;
    TF_R(17) TF_R(29) TF_R(16) TF_R(24);  x0 += ks2; x1 += ks0 + 2u;
    TF_R(13) TF_R(15) TF_R(26) TF_R(6);   x0 += ks0; x1 += ks1 + 3u;
    TF_R(17) TF_R(29) TF_R(16) TF_R(24);  x0 += ks1; x1 += ks2 + 4u;
    TF_R(13) TF_R(15) TF_R(26) TF_R(6);   x0 += ks2; x1 += ks0 + 5u;
#undef TF_R
    o0 = x0; o1 = x1;
}

// jax_threefry_partitionable=True path: counter lanes (0, i), bits = o0 ^ o1.
__device__ __forceinline__ float gumbel_at(uint32_t i) {
    uint32_t o0, o1;
    threefry_42(0u, i, o0, o1);
    uint32_t bits = o0 ^ o1;
    float f = __uint_as_float((bits >> 9) | 0x3F800000u) - 1.0f;   // [0,1)
    const float minv  = (float)1e-6;
    const float maxv  = (float)(1.0 - 1e-6);
    const float scale = maxv - minv;
    float u = __fadd_rn(__fmul_rn(f, scale), minv);  // no FMA contraction
    u = fmaxf(minv, u);
    return -logf(-logf(u));
}

// ---------------------------------------------------------------------------
// Kernel 2: per-row softmax + Gumbel top-k mask. One warp per row.
// ---------------------------------------------------------------------------
__global__ __launch_bounds__(256)
void k_router(const float* __restrict__ logits, const int* __restrict__ kin,
              float* __restrict__ mask, float* __restrict__ weight) {
    const int gw = (int)((blockIdx.x * blockDim.x + threadIdx.x) >> 5);
    const int lane = threadIdx.x & 31;
    if (gw >= T_ROWS) return;

    int K = 8;
    if (kin) { K = *kin; if (K < 0) K = 0; if (K > E_DIM) K = E_DIM; }

    const float* lrow = logits + (size_t)gw * E_DIM;
    float l0 = lrow[lane];
    float l1 = lrow[lane + 32];

    // softmax on clean logits
    float mx = fmaxf(l0, l1);
#pragma unroll
    for (int o = 16; o; o >>= 1) mx = fmaxf(mx, __shfl_xor_sync(0xffffffffu, mx, o));
    float p0 = expf(l0 - mx), p1 = expf(l1 - mx);
    float s = p0 + p1;
#pragma unroll
    for (int o = 16; o; o >>= 1) s += __shfl_xor_sync(0xffffffffu, s, o);
    weight[(size_t)gw * E_DIM + lane]      = p0 / s;
    weight[(size_t)gw * E_DIM + lane + 32] = p1 / s;

    // Gumbel-perturbed selection scores
    const uint32_t base = (uint32_t)gw * 64u;
    float s0 = l0 + gumbel_at(base + (uint32_t)lane);
    float s1 = l1 + gumbel_at(base + (uint32_t)lane + 32u);

    const float NEG_INF = __int_as_float(0xff800000);
    const int e0 = lane, e1 = lane + 32;
    float m0 = 0.0f, m1 = 0.0f;

    for (int kk = 0; kk < K; kk++) {
        float v = s0; int ii = e0;
        if (s1 > v) { v = s1; ii = e1; }   // tie keeps lower index
#pragma unroll
        for (int o = 16; o; o >>= 1) {
            float ov = __shfl_xor_sync(0xffffffffu, v, o);
            int   oi = __shfl_xor_sync(0xffffffffu, ii, o);
            if (ov > v || (ov == v && oi < ii)) { v = ov; ii = oi; }
        }
        if (ii == e0)      { m0 = 1.0f; s0 = NEG_INF; }
        else if (ii == e1) { m1 = 1.0f; s1 = NEG_INF; }
    }

    mask[(size_t)gw * E_DIM + lane]      = m0;
    mask[(size_t)gw * E_DIM + lane + 32] = m1;
}

// ---------------------------------------------------------------------------
// launch: transpose -> GEMM (logits into out slice) -> router
// out layout (f32): [ mask (T*E) | weight (T*E) | logits (T*E) ]
// ---------------------------------------------------------------------------
extern "C" void kernel_launch(void* const* d_in, const int* in_sizes, int n_in,
                              void* d_out, int out_size) {
    const float* h    = (const float*)d_in[0];
    const float* W    = (const float*)d_in[1];
    const float* bias = (const float*)d_in[2];
    const int*   kin  = (n_in > 3 && in_sizes[3] == 1) ? (const int*)d_in[3] : nullptr;

    float* out    = (float*)d_out;
    float* mask   = out;
    float* weight = out + TE;
    float* logits = out + 2 * TE;

    k_transpose<<<D_DIM / 32, 256>>>(W);
    k_gemm<<<T_ROWS / 64, 256>>>(h, bias, logits);
    k_router<<<(T_ROWS * 32) / 256, 256>>>(logits, kin, mask, weight);
}

// round 14
// speedup vs baseline: 2.9138x; 1.4274x over previous
#include <cuda_runtime.h>
#include <cuda_bf16.h>
#include <cstdint>
#include <math.h>

#define T_ROWS 8192
#define D_DIM  4096
#define E_DIM  64
#define TE     (T_ROWS * E_DIM)     // 524288

#define KC        64                 // K per chunk
#define NCH       32                 // chunks per CTA (split-K: 2048 per half)
#define BROW      144                // B smem/gmem row stride bytes (64 bf16 + pad)
#define BTILE     (64 * BROW)        // 9216 B per split per chunk
#define BSTAGE    (3 * BTILE)        // 27648 B per stage
#define SMEM_DYN  (3 * BSTAGE + 256)

// W pre-split into 3 bf16 tile arrays: [split][chunk 64][e 64][BROW bytes]
__device__ __align__(16) unsigned char g_Bb[3 * 64 * BTILE];
// split-K partial for K-half 1
__device__ float g_part[TE];

// ---------------------------------------------------------------------------
// helpers
// ---------------------------------------------------------------------------
__device__ __forceinline__ unsigned sptr(const void* p) {
    return (unsigned)__cvta_generic_to_shared(p);
}
// 3-way bf16 split: a ~= h + m + l (residual cascade, error ~2^-24 |a|)
__device__ __forceinline__ void split3(float a, __nv_bfloat16& bh,
                                       __nv_bfloat16& bm, __nv_bfloat16& bl) {
    bh = __float2bfloat16(a);
    float r1 = a - __bfloat162float(bh);
    bm = __float2bfloat16(r1);
    float r2 = r1 - __bfloat162float(bm);
    bl = __float2bfloat16(r2);
}
__device__ __forceinline__ uint32_t packbf2(__nv_bfloat16 lo, __nv_bfloat16 hi) {
    __nv_bfloat162 v = __halves2bfloat162(lo, hi);
    return *reinterpret_cast<uint32_t*>(&v);
}
// split a float2 (consecutive k) into 3 packed bf16x2 regs (lo = even k)
__device__ __forceinline__ void split_pack(float2 f, uint32_t& ph, uint32_t& pm,
                                           uint32_t& pl) {
    __nv_bfloat16 hx, mx, lx, hy, my, ly;
    split3(f.x, hx, mx, lx);
    split3(f.y, hy, my, ly);
    ph = packbf2(hx, hy);
    pm = packbf2(mx, my);
    pl = packbf2(lx, ly);
}
// m16n8k16 bf16 MMA, fp32 accumulate (baseline PTX, sm_80+)
__device__ __forceinline__ void mma16816(float4& c, const uint32_t a[4],
                                         uint32_t b0, uint32_t b1) {
    asm volatile(
        "mma.sync.aligned.m16n8k16.row.col.f32.bf16.bf16.f32 "
        "{%0,%1,%2,%3}, {%4,%5,%6,%7}, {%8,%9}, {%0,%1,%2,%3};"
        : "+f"(c.x), "+f"(c.y), "+f"(c.z), "+f"(c.w)
        : "r"(a[0]), "r"(a[1]), "r"(a[2]), "r"(a[3]), "r"(b0), "r"(b1));
}
__device__ __forceinline__ uint32_t lds32(uint32_t addr) {
    uint32_t v;
    asm volatile("ld.shared.b32 %0, [%1];" : "=r"(v) : "r"(addr));
    return v;
}

// ---------------------------------------------------------------------------
// Kernel 0: split W[E][D] fp32 -> 3 bf16 chunk tiles, row stride 144 B
// ---------------------------------------------------------------------------
__global__ void k_prep_b(const float* __restrict__ W) {
    int task = blockIdx.x * 256 + threadIdx.x;      // 65536 = E * D/4
    int e = task >> 10;
    int k = (task & 1023) * 4;
    float4 w = *(const float4*)(W + (size_t)e * D_DIM + k);
    int chunk = k >> 6;
    int kk = k & 63;
    __nv_bfloat16 h[4], m[4], l[4];
    split3(w.x, h[0], m[0], l[0]);
    split3(w.y, h[1], m[1], l[1]);
    split3(w.z, h[2], m[2], l[2]);
    split3(w.w, h[3], m[3], l[3]);
    size_t base = (size_t)e * BROW + (size_t)kk * 2;
#pragma unroll
    for (int sp = 0; sp < 3; sp++) {
        const __nv_bfloat16* v = (sp == 0) ? h : (sp == 1) ? m : l;
        uint2 pk = make_uint2(packbf2(v[0], v[1]), packbf2(v[2], v[3]));
        *(uint2*)(g_Bb + (size_t)(sp * 64 + chunk) * BTILE + base) = pk;
    }
}

// ---------------------------------------------------------------------------
// Kernel 1: HMMA GEMM. 128 CTAs = 64 m-tiles x 2 k-halves.
//   256 thr = 8 warps; warp w -> rows [w*16, w*16+16), all 64 cols.
//   6 products (hh,hm,mh,hl,lh,mm) into HMMA accumulators, drained to fp32
//   master registers every 2 chunks (bounds tensor-core alignment-truncation
//   bias to ~2e-7; drain adds are RN fp32).
//   kh=0 writes logits(+bias), kh=1 writes g_part; router sums.
// ---------------------------------------------------------------------------
__global__ __launch_bounds__(256, 1)
void k_gemm_hmma(const float* __restrict__ h, const float* __restrict__ bias,
                 float* __restrict__ logits) {
    extern __shared__ __align__(16) unsigned char smem_raw[];
    const uint32_t sB = sptr(smem_raw);

    const int tid = threadIdx.x;
    const int w = tid >> 5;
    const int lane = tid & 31;
    const int mt = blockIdx.x >> 1;
    const int kh = blockIdx.x & 1;
    const int row0 = mt * 128;

    const int lr = lane >> 2;          // row-in-group 0..7
    const int lq = lane & 3;           // quad col id

    // per-lane A base: row (row0 + w*16 + lr), k half offset, col (lq*2)
    const float* hA = h + (size_t)(row0 + w * 16 + lr) * D_DIM + kh * 2048 + lq * 2;

#define PF_B(C, S) do {                                                       \
    size_t _srcb = (size_t)(kh * 32 + (C)) * BTILE;                           \
    _Pragma("unroll")                                                         \
    for (int _j = 0; _j < 7; _j++) {                                          \
        int _i = tid + 256 * _j;                                              \
        if (_i < BSTAGE / 16) {                                               \
            int _sp = _i / (BTILE / 16);                                      \
            int _wo = _i % (BTILE / 16);                                      \
            unsigned _d = sB + (S) * BSTAGE + _sp * BTILE + _wo * 16;         \
            const unsigned char* _s =                                         \
                g_Bb + (size_t)_sp * 64 * BTILE + _srcb + (size_t)_wo * 16;   \
            asm volatile("cp.async.ca.shared.global [%0], [%1], 16;"          \
                         :: "r"(_d), "l"(_s));                                \
        }                                                                     \
    }                                                                         \
    asm volatile("cp.async.commit_group;");                                   \
} while (0)

    float4 acc[8];      // HMMA window accumulators (reset every 2 chunks)
    float4 master[8];   // fp32 RN master sums
#pragma unroll
    for (int j = 0; j < 8; j++) {
        acc[j]    = make_float4(0.f, 0.f, 0.f, 0.f);
        master[j] = make_float4(0.f, 0.f, 0.f, 0.f);
    }

    PF_B(0, 0);
    PF_B(1, 1);

    // A regs for chunk 0
    float2 rA[16];
#pragma unroll
    for (int s = 0; s < 4; s++) {
        const float* p = hA + s * 16;
        rA[s * 4 + 0] = *(const float2*)(p);
        rA[s * 4 + 1] = *(const float2*)(p + 8 * D_DIM);
        rA[s * 4 + 2] = *(const float2*)(p + 8);
        rA[s * 4 + 3] = *(const float2*)(p + 8 * D_DIM + 8);
    }

    for (int c = 0; c < NCH; c++) {
        if (c < NCH - 1) asm volatile("cp.async.wait_group 1;");
        else             asm volatile("cp.async.wait_group 0;");
        __syncthreads();
        if (c + 2 < NCH) PF_B(c + 2, (c + 2) % 3);

        // prefetch next chunk's A
        float2 rAn[16];
        if (c + 1 < NCH) {
            const float* pc = hA + (c + 1) * KC;
#pragma unroll
            for (int s = 0; s < 4; s++) {
                const float* p = pc + s * 16;
                rAn[s * 4 + 0] = *(const float2*)(p);
                rAn[s * 4 + 1] = *(const float2*)(p + 8 * D_DIM);
                rAn[s * 4 + 2] = *(const float2*)(p + 8);
                rAn[s * 4 + 3] = *(const float2*)(p + 8 * D_DIM + 8);
            }
        }

        const uint32_t stg = sB + (c % 3) * BSTAGE;
        const uint32_t bbase = stg + (uint32_t)lr * BROW + (uint32_t)lq * 4;

#pragma unroll
        for (int s = 0; s < 4; s++) {
            uint32_t ah[4], am[4], al[4];
            split_pack(rA[s * 4 + 0], ah[0], am[0], al[0]);
            split_pack(rA[s * 4 + 1], ah[1], am[1], al[1]);
            split_pack(rA[s * 4 + 2], ah[2], am[2], al[2]);
            split_pack(rA[s * 4 + 3], ah[3], am[3], al[3]);

            const uint32_t bs = bbase + (uint32_t)s * 32;
#pragma unroll
            for (int j = 0; j < 8; j++) {
                uint32_t ro = bs + (uint32_t)j * (8 * BROW);
                uint32_t bh0 = lds32(ro),              bh1 = lds32(ro + 16);
                uint32_t bm0 = lds32(ro + BTILE),      bm1 = lds32(ro + BTILE + 16);
                uint32_t bl0 = lds32(ro + 2 * BTILE),  bl1 = lds32(ro + 2 * BTILE + 16);
                mma16816(acc[j], ah, bh0, bh1);   // hh
                mma16816(acc[j], am, bh0, bh1);   // mh
                mma16816(acc[j], al, bh0, bh1);   // lh
                mma16816(acc[j], ah, bm0, bm1);   // hm
                mma16816(acc[j], am, bm0, bm1);   // mm
                mma16816(acc[j], ah, bl0, bl1);   // hl
            }
        }

        // drain HMMA window into fp32 master every 2 chunks
        if ((c & 1) == 1) {
#pragma unroll
            for (int j = 0; j < 8; j++) {
                master[j].x += acc[j].x;
                master[j].y += acc[j].y;
                master[j].z += acc[j].z;
                master[j].w += acc[j].w;
                acc[j] = make_float4(0.f, 0.f, 0.f, 0.f);
            }
        }

#pragma unroll
        for (int i = 0; i < 16; i++) rA[i] = rAn[i];
    }

    // epilogue (NCH even -> all windows drained)
    float* dst = (kh == 0) ? logits : g_part;
    const int rg = row0 + w * 16 + lr;
#pragma unroll
    for (int j = 0; j < 8; j++) {
        int col = j * 8 + lq * 2;
        float b0 = (kh == 0) ? __ldg(bias + col)     : 0.f;
        float b1 = (kh == 0) ? __ldg(bias + col + 1) : 0.f;
        *(float2*)(dst + (size_t)rg * E_DIM + col) =
            make_float2(master[j].x + b0, master[j].y + b1);
        *(float2*)(dst + (size_t)(rg + 8) * E_DIM + col) =
            make_float2(master[j].z + b0, master[j].w + b1);
    }
#undef PF_B
}

// ---------------------------------------------------------------------------
// JAX threefry2x32, key = jax.random.key(42) -> (0, 42)
// ---------------------------------------------------------------------------
__device__ __forceinline__ uint32_t rotl32(uint32_t x, int r) {
    return __funnelshift_l(x, x, r);
}
__device__ __forceinline__ void threefry_42(uint32_t c0, uint32_t c1,
                                            uint32_t& o0, uint32_t& o1) {
    const uint32_t ks0 = 0u, ks1 = 42u, ks2 = 0x1BD11BDAu ^ 0u ^ 42u;
    uint32_t x0 = c0 + ks0, x1 = c1 + ks1;
#define TF_R(r) { x0 += x1; x1 = rotl32(x1, (r)); x1 ^= x0; }
    TF_R(13) TF_R(15) TF_R(26) TF_R(6);   x0 += ks1; x1 += ks2 + 1u;
    TF_R(17) TF_R(29) TF_R(16) TF_R(24);  x0 += ks2; x1 += ks0 + 2u;
    TF_R(13) TF_R(15) TF_R(26) TF_R(6);   x0 += ks0; x1 += ks1 + 3u;
    TF_R(17) TF_R(29) TF_R(16) TF_R(24);  x0 += ks1; x1 += ks2 + 4u;
    TF_R(13) TF_R(15) TF_R(26) TF_R(6);   x0 += ks2; x1 += ks0 + 5u;
#undef TF_R
    o0 = x0; o1 = x1;
}
// partitionable path: counter lanes (0, i), bits = o0 ^ o1
__device__ __forceinline__ float gumbel_at(uint32_t i) {
    uint32_t o0, o1;
    threefry_42(0u, i, o0, o1);
    uint32_t bits = o0 ^ o1;
    float f = __uint_as_float((bits >> 9) | 0x3F800000u) - 1.0f;
    const float minv  = (float)1e-6;
    const float maxv  = (float)(1.0 - 1e-6);
    const float scale = maxv - minv;
    float u = __fadd_rn(__fmul_rn(f, scale), minv);
    u = fmaxf(minv, u);
    return -logf(-logf(u));
}

// ---------------------------------------------------------------------------
// Kernel 2: sum split-K partials -> final logits; softmax + Gumbel top-k.
// One warp per row.
// ---------------------------------------------------------------------------
__global__ __launch_bounds__(256)
void k_router(float* __restrict__ logits, const int* __restrict__ kin,
              float* __restrict__ mask, float* __restrict__ weight) {
    const int gw = (int)((blockIdx.x * blockDim.x + threadIdx.x) >> 5);
    const int lane = threadIdx.x & 31;
    if (gw >= T_ROWS) return;

    int K = 8;
    if (kin) { K = *kin; if (K < 0) K = 0; if (K > E_DIM) K = E_DIM; }

    const size_t i0 = (size_t)gw * E_DIM + lane;
    const size_t i1 = i0 + 32;
    float l0 = logits[i0] + g_part[i0];
    float l1 = logits[i1] + g_part[i1];
    logits[i0] = l0;          // final logits output
    logits[i1] = l1;

    float mx = fmaxf(l0, l1);
#pragma unroll
    for (int o = 16; o; o >>= 1) mx = fmaxf(mx, __shfl_xor_sync(0xffffffffu, mx, o));
    float p0 = expf(l0 - mx), p1 = expf(l1 - mx);
    float s = p0 + p1;
#pragma unroll
    for (int o = 16; o; o >>= 1) s += __shfl_xor_sync(0xffffffffu, s, o);
    weight[i0] = p0 / s;
    weight[i1] = p1 / s;

    const uint32_t base = (uint32_t)gw * 64u;
    float s0 = l0 + gumbel_at(base + (uint32_t)lane);
    float s1 = l1 + gumbel_at(base + (uint32_t)lane + 32u);

    const float NEG_INF = __int_as_float(0xff800000);
    const int e0 = lane, e1 = lane + 32;
    float m0 = 0.0f, m1 = 0.0f;

    for (int kk = 0; kk < K; kk++) {
        float v = s0; int ii = e0;
        if (s1 > v) { v = s1; ii = e1; }
#pragma unroll
        for (int o = 16; o; o >>= 1) {
            float ov = __shfl_xor_sync(0xffffffffu, v, o);
            int   oi = __shfl_xor_sync(0xffffffffu, ii, o);
            if (ov > v || (ov == v && oi < ii)) { v = ov; ii = oi; }
        }
        if (ii == e0)      { m0 = 1.0f; s0 = NEG_INF; }
        else if (ii == e1) { m1 = 1.0f; s1 = NEG_INF; }
    }

    mask[i0] = m0;
    mask[i1] = m1;
}

// ---------------------------------------------------------------------------
// launch: prep W splits -> HMMA split-K GEMM -> router (sum + topk)
// out layout (f32): [ mask (T*E) | weight (T*E) | logits (T*E) ]
// ---------------------------------------------------------------------------
extern "C" void kernel_launch(void* const* d_in, const int* in_sizes, int n_in,
                              void* d_out, int out_size) {
    const float* h    = (const float*)d_in[0];
    const float* W    = (const float*)d_in[1];
    const float* bias = (const float*)d_in[2];
    const int*   kin  = (n_in > 3 && in_sizes[3] == 1) ? (const int*)d_in[3] : nullptr;

    float* out    = (float*)d_out;
    float* mask   = out;
    float* weight = out + TE;
    float* logits = out + 2 * TE;

    cudaFuncSetAttribute(k_gemm_hmma,
                         cudaFuncAttributeMaxDynamicSharedMemorySize, SMEM_DYN);

    k_prep_b<<<256, 256>>>(W);
    k_gemm_hmma<<<128, 256, SMEM_DYN>>>(h, bias, logits);
    k_router<<<(T_ROWS * 32) / 256, 256>>>(logits, kin, mask, weight);
}

// round 15
// speedup vs baseline: 4.0122x; 1.3769x over previous
#include <cuda_runtime.h>
#include <cuda_fp16.h>
#include <cstdint>
#include <math.h>

#define T_ROWS 8192
#define D_DIM  4096
#define E_DIM  64
#define TE     (T_ROWS * E_DIM)     // 524288

#define KC        64                 // K per chunk
#define NCH       32                 // chunks per CTA (split-K: 2048 per half)
#define BROW      144                // B row stride bytes (64 fp16 = 128B + pad)
#define BTILE     (64 * BROW)        // 9216 B per split per chunk
#define BSTAGE    (2 * BTILE)        // 18432 B per stage (2 splits)
#define SMEM_DYN  (3 * BSTAGE + 256)

#define BSCALE    4096.0f            // 2^12, exact
#define BSCALE_INV (1.0f / 4096.0f)

// W pre-scaled by 2^12 and split into 2 fp16 tiles: [split][chunk 64][e 64][BROW]
__device__ __align__(16) unsigned char g_Bb[2 * 64 * BTILE];
// split-K partial for K-half 1
__device__ float g_part[TE];

// ---------------------------------------------------------------------------
// helpers
// ---------------------------------------------------------------------------
__device__ __forceinline__ unsigned sptr(const void* p) {
    return (unsigned)__cvta_generic_to_shared(p);
}
__device__ __forceinline__ uint32_t packh2(__half lo, __half hi) {
    __half2 v = __halves2half2(lo, hi);
    return *reinterpret_cast<uint32_t*>(&v);
}
// 2-way fp16 split: a ~= h + l (residual error ~2^-22 |a|)
__device__ __forceinline__ void split2(float a, __half& h, __half& l) {
    h = __float2half_rn(a);
    float r = a - __half2float(h);
    l = __float2half_rn(r);
}
// split a float2 (consecutive k) into hi/lo packed fp16x2
__device__ __forceinline__ void split_pack2(float2 f, uint32_t& ph, uint32_t& pl) {
    __half hx, lx, hy, ly;
    split2(f.x, hx, lx);
    split2(f.y, hy, ly);
    ph = packh2(hx, hy);
    pl = packh2(lx, ly);
}
// m16n8k16 fp16 MMA, fp32 accumulate (baseline PTX, sm_80+)
__device__ __forceinline__ void mma16816(float4& c, const uint32_t a[4],
                                         uint32_t b0, uint32_t b1) {
    asm volatile(
        "mma.sync.aligned.m16n8k16.row.col.f32.f16.f16.f32 "
        "{%0,%1,%2,%3}, {%4,%5,%6,%7}, {%8,%9}, {%0,%1,%2,%3};"
        : "+f"(c.x), "+f"(c.y), "+f"(c.z), "+f"(c.w)
        : "r"(a[0]), "r"(a[1]), "r"(a[2]), "r"(a[3]), "r"(b0), "r"(b1));
}
__device__ __forceinline__ uint32_t lds32(uint32_t addr) {
    uint32_t v;
    asm volatile("ld.shared.b32 %0, [%1];" : "=r"(v) : "r"(addr));
    return v;
}

// ---------------------------------------------------------------------------
// Kernel 0: W[E][D] fp32 -> x4096 -> 2 fp16 chunk tiles, row stride 144 B
// ---------------------------------------------------------------------------
__global__ void k_prep_b(const float* __restrict__ W) {
    int task = blockIdx.x * 256 + threadIdx.x;      // 65536 = E * D/4
    int e = task >> 10;
    int k = (task & 1023) * 4;
    float4 w = *(const float4*)(W + (size_t)e * D_DIM + k);
    w.x *= BSCALE; w.y *= BSCALE; w.z *= BSCALE; w.w *= BSCALE;
    int chunk = k >> 6;
    int kk = k & 63;
    __half h[4], l[4];
    split2(w.x, h[0], l[0]);
    split2(w.y, h[1], l[1]);
    split2(w.z, h[2], l[2]);
    split2(w.w, h[3], l[3]);
    size_t base = (size_t)e * BROW + (size_t)kk * 2;
    *(uint2*)(g_Bb + (size_t)chunk * BTILE + base) =
        make_uint2(packh2(h[0], h[1]), packh2(h[2], h[3]));
    *(uint2*)(g_Bb + (size_t)(64 + chunk) * BTILE + base) =
        make_uint2(packh2(l[0], l[1]), packh2(l[2], l[3]));
}

// ---------------------------------------------------------------------------
// Kernel 1: HMMA GEMM. 128 CTAs = 64 m-tiles x 2 k-halves.
//   256 thr = 8 warps; warp w -> rows [w*16, w*16+16), all 64 cols.
//   fp16 2-split, 3 products (hh, hl, lh). Accumulators drained to fp32
//   master regs every 2 chunks (bounds HMMA alignment-truncation bias).
//   kh=0 writes logits(+bias), kh=1 writes g_part; router sums.
// ---------------------------------------------------------------------------
__global__ __launch_bounds__(256, 1)
void k_gemm_hmma(const float* __restrict__ h, const float* __restrict__ bias,
                 float* __restrict__ logits) {
    extern __shared__ __align__(16) unsigned char smem_raw[];
    const uint32_t sB = sptr(smem_raw);

    const int tid = threadIdx.x;
    const int w = tid >> 5;
    const int lane = tid & 31;
    const int mt = blockIdx.x >> 1;
    const int kh = blockIdx.x & 1;
    const int row0 = mt * 128;

    const int lr = lane >> 2;          // row-in-group 0..7
    const int lq = lane & 3;           // quad col id

    const float* hA = h + (size_t)(row0 + w * 16 + lr) * D_DIM + kh * 2048 + lq * 2;

#define PF_B(C, S) do {                                                       \
    size_t _srcb = (size_t)(kh * 32 + (C)) * BTILE;                           \
    _Pragma("unroll")                                                         \
    for (int _j = 0; _j < 5; _j++) {                                          \
        int _i = tid + 256 * _j;                                              \
        if (_i < BSTAGE / 16) {                                               \
            int _sp = _i / (BTILE / 16);                                      \
            int _wo = _i % (BTILE / 16);                                      \
            unsigned _d = sB + (S) * BSTAGE + _sp * BTILE + _wo * 16;         \
            const unsigned char* _s =                                         \
                g_Bb + (size_t)_sp * 64 * BTILE + _srcb + (size_t)_wo * 16;   \
            asm volatile("cp.async.ca.shared.global [%0], [%1], 16;"          \
                         :: "r"(_d), "l"(_s));                                \
        }                                                                     \
    }                                                                         \
    asm volatile("cp.async.commit_group;");                                   \
} while (0)

    float4 acc[8];      // HMMA window accumulators (reset every 2 chunks)
    float4 master[8];   // fp32 RN master sums
#pragma unroll
    for (int j = 0; j < 8; j++) {
        acc[j]    = make_float4(0.f, 0.f, 0.f, 0.f);
        master[j] = make_float4(0.f, 0.f, 0.f, 0.f);
    }

    PF_B(0, 0);
    PF_B(1, 1);

    // A regs for chunk 0
    float2 rA[16];
#pragma unroll
    for (int s = 0; s < 4; s++) {
        const float* p = hA + s * 16;
        rA[s * 4 + 0] = *(const float2*)(p);
        rA[s * 4 + 1] = *(const float2*)(p + 8 * D_DIM);
        rA[s * 4 + 2] = *(const float2*)(p + 8);
        rA[s * 4 + 3] = *(const float2*)(p + 8 * D_DIM + 8);
    }

    for (int c = 0; c < NCH; c++) {
        if (c < NCH - 1) asm volatile("cp.async.wait_group 1;");
        else             asm volatile("cp.async.wait_group 0;");
        __syncthreads();
        if (c + 2 < NCH) PF_B(c + 2, (c + 2) % 3);

        // prefetch next chunk's A
        float2 rAn[16];
        if (c + 1 < NCH) {
            const float* pc = hA + (c + 1) * KC;
#pragma unroll
            for (int s = 0; s < 4; s++) {
                const float* p = pc + s * 16;
                rAn[s * 4 + 0] = *(const float2*)(p);
                rAn[s * 4 + 1] = *(const float2*)(p + 8 * D_DIM);
                rAn[s * 4 + 2] = *(const float2*)(p + 8);
                rAn[s * 4 + 3] = *(const float2*)(p + 8 * D_DIM + 8);
            }
        }

        const uint32_t stg = sB + (c % 3) * BSTAGE;
        const uint32_t bbase = stg + (uint32_t)lr * BROW + (uint32_t)lq * 4;

#pragma unroll
        for (int s = 0; s < 4; s++) {
            uint32_t ah[4], al[4];
            split_pack2(rA[s * 4 + 0], ah[0], al[0]);
            split_pack2(rA[s * 4 + 1], ah[1], al[1]);
            split_pack2(rA[s * 4 + 2], ah[2], al[2]);
            split_pack2(rA[s * 4 + 3], ah[3], al[3]);

            const uint32_t bs = bbase + (uint32_t)s * 32;
#pragma unroll
            for (int j = 0; j < 8; j++) {
                uint32_t ro = bs + (uint32_t)j * (8 * BROW);
                uint32_t bh0 = lds32(ro),         bh1 = lds32(ro + 16);
                uint32_t bl0 = lds32(ro + BTILE), bl1 = lds32(ro + BTILE + 16);
                mma16816(acc[j], ah, bh0, bh1);   // hh
                mma16816(acc[j], ah, bl0, bl1);   // hl
                mma16816(acc[j], al, bh0, bh1);   // lh
            }
        }

        // drain HMMA window into fp32 master every 2 chunks
        if ((c & 1) == 1) {
#pragma unroll
            for (int j = 0; j < 8; j++) {
                master[j].x += acc[j].x;
                master[j].y += acc[j].y;
                master[j].z += acc[j].z;
                master[j].w += acc[j].w;
                acc[j] = make_float4(0.f, 0.f, 0.f, 0.f);
            }
        }

#pragma unroll
        for (int i = 0; i < 16; i++) rA[i] = rAn[i];
    }

    // epilogue: undo B scale (exact 2^-12), add bias on kh=0
    float* dst = (kh == 0) ? logits : g_part;
    const int rg = row0 + w * 16 + lr;
#pragma unroll
    for (int j = 0; j < 8; j++) {
        int col = j * 8 + lq * 2;
        float b0 = (kh == 0) ? __ldg(bias + col)     : 0.f;
        float b1 = (kh == 0) ? __ldg(bias + col + 1) : 0.f;
        *(float2*)(dst + (size_t)rg * E_DIM + col) =
            make_float2(master[j].x * BSCALE_INV + b0,
                        master[j].y * BSCALE_INV + b1);
        *(float2*)(dst + (size_t)(rg + 8) * E_DIM + col) =
            make_float2(master[j].z * BSCALE_INV + b0,
                        master[j].w * BSCALE_INV + b1);
    }
#undef PF_B
}

// ---------------------------------------------------------------------------
// JAX threefry2x32, key = jax.random.key(42) -> (0, 42)
// ---------------------------------------------------------------------------
__device__ __forceinline__ uint32_t rotl32(uint32_t x, int r) {
    return __funnelshift_l(x, x, r);
}
__device__ __forceinline__ void threefry_42(uint32_t c0, uint32_t c1,
                                            uint32_t& o0, uint32_t& o1) {
    const uint32_t ks0 = 0u, ks1 = 42u, ks2 = 0x1BD11BDAu ^ 0u ^ 42u;
    uint32_t x0 = c0 + ks0, x1 = c1 + ks1;
#define TF_R(r) { x0 += x1; x1 = rotl32(x1, (r)); x1 ^= x0; }
    TF_R(13) TF_R(15) TF_R(26) TF_R(6);   x0 += ks1; x1 += ks2 + 1u;
    TF_R(17) TF_R(29) TF_R(16) TF_R(24);  x0 += ks2; x1 += ks0 + 2u;
    TF_R(13) TF_R(15) TF_R(26) TF_R(6);   x0 += ks0; x1 += ks1 + 3u;
    TF_R(17) TF_R(29) TF_R(16) TF_R(24);  x0 += ks1; x1 += ks2 + 4u;
    TF_R(13) TF_R(15) TF_R(26) TF_R(6);   x0 += ks2; x1 += ks0 + 5u;
#undef TF_R
    o0 = x0; o1 = x1;
}
// partitionable path: counter lanes (0, i), bits = o0 ^ o1
__device__ __forceinline__ float gumbel_at(uint32_t i) {
    uint32_t o0, o1;
    threefry_42(0u, i, o0, o1);
    uint32_t bits = o0 ^ o1;
    float f = __uint_as_float((bits >> 9) | 0x3F800000u) - 1.0f;
    const float minv  = (float)1e-6;
    const float maxv  = (float)(1.0 - 1e-6);
    const float scale = maxv - minv;
    float u = __fadd_rn(__fmul_rn(f, scale), minv);
    u = fmaxf(minv, u);
    return -logf(-logf(u));
}

// ---------------------------------------------------------------------------
// Kernel 2: sum split-K partials -> final logits; softmax + Gumbel top-k.
// One warp per row.
// ---------------------------------------------------------------------------
__global__ __launch_bounds__(256)
void k_router(float* __restrict__ logits, const int* __restrict__ kin,
              float* __restrict__ mask, float* __restrict__ weight) {
    const int gw = (int)((blockIdx.x * blockDim.x + threadIdx.x) >> 5);
    const int lane = threadIdx.x & 31;
    if (gw >= T_ROWS) return;

    int K = 8;
    if (kin) { K = *kin; if (K < 0) K = 0; if (K > E_DIM) K = E_DIM; }

    const size_t i0 = (size_t)gw * E_DIM + lane;
    const size_t i1 = i0 + 32;
    float l0 = logits[i0] + g_part[i0];
    float l1 = logits[i1] + g_part[i1];
    logits[i0] = l0;          // final logits output
    logits[i1] = l1;

    float mx = fmaxf(l0, l1);
#pragma unroll
    for (int o = 16; o; o >>= 1) mx = fmaxf(mx, __shfl_xor_sync(0xffffffffu, mx, o));
    float p0 = expf(l0 - mx), p1 = expf(l1 - mx);
    float s = p0 + p1;
#pragma unroll
    for (int o = 16; o; o >>= 1) s += __shfl_xor_sync(0xffffffffu, s, o);
    weight[i0] = p0 / s;
    weight[i1] = p1 / s;

    const uint32_t base = (uint32_t)gw * 64u;
    float s0 = l0 + gumbel_at(base + (uint32_t)lane);
    float s1 = l1 + gumbel_at(base + (uint32_t)lane + 32u);

    const float NEG_INF = __int_as_float(0xff800000);
    const int e0 = lane, e1 = lane + 32;
    float m0 = 0.0f, m1 = 0.0f;

    for (int kk = 0; kk < K; kk++) {
        float v = s0; int ii = e0;
        if (s1 > v) { v = s1; ii = e1; }
#pragma unroll
        for (int o = 16; o; o >>= 1) {
            float ov = __shfl_xor_sync(0xffffffffu, v, o);
            int   oi = __shfl_xor_sync(0xffffffffu, ii, o);
            if (ov > v || (ov == v && oi < ii)) { v = ov; ii = oi; }
        }
        if (ii == e0)      { m0 = 1.0f; s0 = NEG_INF; }
        else if (ii == e1) { m1 = 1.0f; s1 = NEG_INF; }
    }

    mask[i0] = m0;
    mask[i1] = m1;
}

// ---------------------------------------------------------------------------
// launch: prep W splits -> HMMA split-K GEMM -> router (sum + topk)
// out layout (f32): [ mask (T*E) | weight (T*E) | logits (T*E) ]
// ---------------------------------------------------------------------------
extern "C" void kernel_launch(void* const* d_in, const int* in_sizes, int n_in,
                              void* d_out, int out_size) {
    const float* h    = (const float*)d_in[0];
    const float* W    = (const float*)d_in[1];
    const float* bias = (const float*)d_in[2];
    const int*   kin  = (n_in > 3 && in_sizes[3] == 1) ? (const int*)d_in[3] : nullptr;

    float* out    = (float*)d_out;
    float* mask   = out;
    float* weight = out + TE;
    float* logits = out + 2 * TE;

    cudaFuncSetAttribute(k_gemm_hmma,
                         cudaFuncAttributeMaxDynamicSharedMemorySize, SMEM_DYN);

    k_prep_b<<<256, 256>>>(W);
    k_gemm_hmma<<<128, 256, SMEM_DYN>>>(h, bias, logits);
    k_router<<<(T_ROWS * 32) / 256, 256>>>(logits, kin, mask, weight);
}